// round 15
// baseline (speedup 1.0000x reference)
#include <cuda_runtime.h>
#include <cuda_fp16.h>
#include <cstdint>

#define DTC   0.001f
#define HID   512
#define NOUT  128
#define SEQL  2048
#define NB    64
#define MROWS (SEQL * NB)     // 131072 output rows, m = s*64 + b
#define NCH   (NB * NOUT)     // 8192 recurrence chains
#define SEG_P 32
#define SEG_L 64

// ---------------- scratch (no allocation allowed) ----------------
__device__ __align__(16) __half g_Wh[NOUT * HID];
__device__ float g_agg_v[SEG_P * NCH];
__device__ float g_agg_i[SEG_P * NCH];
__device__ float g_inc_v[SEG_P * NCH];
__device__ float g_inc_i[SEG_P * NCH];
__device__ int   g_flag [SEG_P * NCH];   // 0 = none, 1 = aggregate, 2 = inclusive

// ---------------- helpers ----------------
__device__ __forceinline__ uint32_t smem_u32(const void* p) {
    uint32_t a;
    asm("{ .reg .u64 t; cvta.to.shared.u64 t, %1; cvt.u32.u64 %0, t; }" : "=r"(a) : "l"(p));
    return a;
}
__device__ __forceinline__ void ldsm_x4(uint32_t* r, uint32_t addr) {
    asm volatile("ldmatrix.sync.aligned.m8n8.x4.shared.b16 {%0,%1,%2,%3}, [%4];"
                 : "=r"(r[0]), "=r"(r[1]), "=r"(r[2]), "=r"(r[3]) : "r"(addr));
}
__device__ __forceinline__ void mma_f16(float* c, const uint32_t* a,
                                        uint32_t b0, uint32_t b1) {
    asm volatile(
        "mma.sync.aligned.m16n8k16.row.col.f32.f16.f16.f32 "
        "{%0,%1,%2,%3}, {%4,%5,%6,%7}, {%8,%9}, {%0,%1,%2,%3};"
        : "+f"(c[0]), "+f"(c[1]), "+f"(c[2]), "+f"(c[3])
        : "r"(a[0]), "r"(a[1]), "r"(a[2]), "r"(a[3]), "r"(b0), "r"(b1));
}
__device__ __forceinline__ void cp16(uint32_t smaddr, const void* g) {
    asm volatile("cp.async.cg.shared.global [%0], [%1], 16;"
                 :: "r"(smaddr), "l"(g) : "memory");
}
#define CP_COMMIT() asm volatile("cp.async.commit_group;" ::: "memory")
#define CP_WAIT0()  asm volatile("cp.async.wait_group 0;" ::: "memory")

__device__ __forceinline__ uint32_t h2u(__half2 v) {
    return *reinterpret_cast<uint32_t*>(&v);
}
__device__ __forceinline__ uint2 cvt4h(float4 f) {
    uint2 r;
    r.x = h2u(__floats2half2_rn(f.x, f.y));
    r.y = h2u(__floats2half2_rn(f.z, f.w));
    return r;
}

// ---------------------------------------------------------------------------
__global__ __launch_bounds__(256)
void w_preconv(const float* __restrict__ W) {
    const int i = blockIdx.x * 256 + threadIdx.x;
    g_Wh[i] = __float2half_rn(W[i]);
}

__global__ __launch_bounds__(256)
void flag_reset() {
    g_flag[blockIdx.x * 256 + threadIdx.x] = 0;
}

// ---------------------------------------------------------------------------
// GEMM (R12, proven 137.2us config): z = fp16(x)*fp16(W), fp32 accumulate.
// CTA 128x128, BK=32 (16 chunks), double-buffered, 256 threads / 8 warps,
// warp tile 64x32, 2 CTAs per SM. SMEM rows 64B padded to 80B.
// ---------------------------------------------------------------------------
#define ROWB   80
#define MATB   (128 * ROWB)          // 10240 bytes per matrix
#define BUFB   (2 * MATB)            // Ah, B = 20480
#define SMEMB  (2 * BUFB)            // 40960 bytes

extern __shared__ char dynsmem[];

__global__ __launch_bounds__(256, 2)
void snn_gemm_f16(const float* __restrict__ x, float* __restrict__ z) {
    const int tid  = threadIdx.x;
    const int wid  = tid >> 5;
    const int lane = tid & 31;
    const int m0   = blockIdx.x * 128;
    const int wm   = wid & 1;
    const int wn   = wid >> 1;

    const uint32_t sm = smem_u32(dynsmem);

    const int rA = tid >> 1;
    const int hA = (tid & 1) * 16;
    const int mA = m0 + rA;
    const float* pA = x + ((size_t)(mA & 63) * SEQL + (size_t)(mA >> 6)) * HID + hA;
    const uint32_t st0 = (uint32_t)rA * ROWB + (uint32_t)hA * 2;

    const __half* pB = g_Wh + (size_t)rA * HID + hA;
    const uint32_t bDst = (uint32_t)MATB + st0;

    uint32_t aAddr[4];
#pragma unroll
    for (int i = 0; i < 4; i++) {
        const int arow = wm * 64 + i * 16 + (lane & 15);
        aAddr[i] = sm + (uint32_t)arow * ROWB + ((lane >> 4) & 1) * 16;
    }
    uint32_t bAddr[2];
#pragma unroll
    for (int g = 0; g < 2; g++) {
        const int bcol = wn * 32 + g * 16 + ((lane >> 4) & 1) * 8 + (lane & 7);
        bAddr[g] = sm + (uint32_t)MATB + (uint32_t)bcol * ROWB +
                   ((lane >> 3) & 1) * 16;
    }

    float acc[4][4][4];
#pragma unroll
    for (int i = 0; i < 4; i++)
#pragma unroll
        for (int j = 0; j < 4; j++)
#pragma unroll
            for (int q = 0; q < 4; q++) acc[i][j][q] = 0.f;

    float4 rgA[4];
    auto loadA = [&](int c) {
#pragma unroll
        for (int q = 0; q < 4; q++) rgA[q] = *(const float4*)(pA + c * 32 + q * 4);
    };
    auto storeA = [&](char* base) {
#pragma unroll
        for (int q = 0; q < 4; q++)
            *(uint2*)(base + st0 + (uint32_t)q * 8) = cvt4h(rgA[q]);
    };
    auto cpB = [&](uint32_t bufb, int c) {
        cp16(sm + bufb + bDst, pB + c * 32);
        cp16(sm + bufb + bDst + 16, pB + c * 32 + 8);
    };

    loadA(0);
    storeA(dynsmem);
    cpB(0, 0);
    CP_COMMIT();
    loadA(1);

    for (int c = 0; c < 16; c++) {
        const int cb = c & 1;
        CP_WAIT0();
        __syncthreads();
        if (c < 15) {
            storeA(dynsmem + (cb ^ 1) * BUFB);
            cpB((uint32_t)(cb ^ 1) * BUFB, c + 1);
            CP_COMMIT();
            if (c < 14) loadA(c + 2);
        }
        const uint32_t bb = (uint32_t)cb * BUFB;
#pragma unroll
        for (int ks = 0; ks < 2; ks++) {
            const uint32_t ko = (uint32_t)ks * 32;
            uint32_t a[4][4];
#pragma unroll
            for (int i = 0; i < 4; i++)
                ldsm_x4(a[i], aAddr[i] + bb + ko);
            uint32_t b[8];
            ldsm_x4(b + 0, bAddr[0] + bb + ko);
            ldsm_x4(b + 4, bAddr[1] + bb + ko);
#pragma unroll
            for (int i = 0; i < 4; i++)
#pragma unroll
                for (int j = 0; j < 4; j++)
                    mma_f16(acc[i][j], a[i], b[2 * j], b[2 * j + 1]);
        }
    }

    const int r0 = lane >> 2;
    const int c0 = (lane & 3) * 2;
#pragma unroll
    for (int i = 0; i < 4; i++) {
        const int mrow = m0 + wm * 64 + i * 16 + r0;
#pragma unroll
        for (int j = 0; j < 4; j++) {
            const int col = wn * 32 + j * 8 + c0;
            *(float2*)&z[(size_t)mrow * NOUT + col] =
                make_float2(acc[i][j][0], acc[i][j][1]);
            *(float2*)&z[(size_t)(mrow + 8) * NOUT + col] =
                make_float2(acc[i][j][2], acc[i][j][3]);
        }
    }
}

// ---------------------------------------------------------------------------
// Single-pass scan with decoupled lookback.
// One thread per (chain, segment): local zero-init scan (64 voltages in regs),
// publish aggregate, look back to obtain exclusive prefix (affine composition
// with incrementally powered M^L), publish inclusive, apply correction, write.
// Block order: segment index p = globalIdx>>13 increases with blockIdx.
// ---------------------------------------------------------------------------
__global__ __launch_bounds__(256)
void scan_onepass(float* __restrict__ zv, float* __restrict__ vf,
                  float* __restrict__ iff,
                  const float* __restrict__ tau_syn,
                  const float* __restrict__ tau_mem, int write_finals) {
    const int g  = blockIdx.x * 256 + threadIdx.x;   // 0 .. SEG_P*NCH-1
    const int ch = g & (NCH - 1);
    const int p  = g >> 13;
    const int idx = p * NCH + ch;

    const float tm = fminf(fmaxf(tau_mem[0], 0.f), 1.f);
    const float ts = fminf(fmaxf(tau_syn[0], 0.f), 1.f);
    const float A = DTC * tm, B = DTC * ts;
    const float a = 1.f - A, b = 1.f - B;

    // M^SEG_L coefficients (same for all threads)
    float la = 1.f, lc = 0.f, lb = 1.f;
#pragma unroll
    for (int k = 0; k < SEG_L; k++) {
        lc = a * lc + A * lb;
        la = a * la;
        lb = b * lb;
    }

    // ---- local zero-init scan, keep voltages in registers ----
    float* zp = zv + (size_t)(p * SEG_L) * NCH + ch;
    float vloc[SEG_L];
    float v = 0.f, cur = 0.f;
    float zb[8];
#pragma unroll
    for (int gg = 0; gg < SEG_L; gg += 8) {
#pragma unroll
        for (int j = 0; j < 8; j++) zb[j] = zp[(gg + j) * NCH];
#pragma unroll
        for (int j = 0; j < 8; j++) {
            v = fmaf(A, cur - v, v);
            vloc[gg + j] = v;
            cur = fmaf(-B, cur, cur) + zb[j];
        }
    }
    const float ev = v, ei = cur;   // segment aggregate (zero-init end state)

    // ---- publish aggregate ----
    g_agg_v[idx] = ev;
    g_agg_i[idx] = ei;
    __threadfence();
    *(volatile int*)&g_flag[idx] = 1;

    // ---- lookback: exclusive prefix (x0v, x0i) = state entering this segment
    float x0v = 0.f, x0i = 0.f;
    if (p > 0) {
        float Pa = 1.f, Pc = 0.f, Pb = 1.f;   // power of M^L accumulated
        int q = p - 1;
        while (true) {
            const int qi = q * NCH + ch;
            int f;
            while ((f = *(volatile int*)&g_flag[qi]) == 0) {}
            __threadfence();
            if (f == 2) {
                const float iv = *(volatile float*)&g_inc_v[qi];
                const float ii = *(volatile float*)&g_inc_i[qi];
                x0v += Pa * iv + Pc * ii;
                x0i += Pb * ii;
                break;
            } else {
                const float av = *(volatile float*)&g_agg_v[qi];
                const float ai = *(volatile float*)&g_agg_i[qi];
                x0v += Pa * av + Pc * ai;
                x0i += Pb * ai;
                if (q == 0) break;           // full prefix assembled
                const float nPa = Pa * la;
                const float nPc = Pa * lc + Pc * lb;
                const float nPb = Pb * lb;
                Pa = nPa; Pc = nPc; Pb = nPb;
                q--;
            }
        }
    }

    // ---- publish inclusive prefix: I_p = M^L * x0 + agg ----
    const float iv = la * x0v + lc * x0i + ev;
    const float ii = lb * x0i + ei;
    g_inc_v[idx] = iv;
    g_inc_i[idx] = ii;
    __threadfence();
    *(volatile int*)&g_flag[idx] = 2;

    // ---- correction + write: out_j = vloc[j] + [M^{j+1}]00*x0v + [M^{j+1}]01*x0i
    float ca = 1.f, cc = 0.f, cb = 1.f;
#pragma unroll
    for (int gg = 0; gg < SEG_L; gg += 8) {
        float ob[8];
#pragma unroll
        for (int j = 0; j < 8; j++) {
            cc = a * cc + A * cb;
            ca = a * ca;
            cb = b * cb;
            ob[j] = vloc[gg + j] + ca * x0v + cc * x0i;
        }
#pragma unroll
        for (int j = 0; j < 8; j++) zp[(gg + j) * NCH] = ob[j];
    }

    if (write_finals && p == SEG_P - 1) {
        vf[ch]  = iv;
        iff[ch] = ii;
    }
}

// ---------------------------------------------------------------------------
extern "C" void kernel_launch(void* const* d_in, const int* in_sizes, int n_in,
                              void* d_out, int out_size) {
    const float* x = nullptr;
    const float* W = nullptr;
    const float* t_syn = nullptr;
    const float* t_mem = nullptr;
    for (int i = 0; i < n_in; i++) {
        if (in_sizes[i] == MROWS * HID)     x = (const float*)d_in[i];
        else if (in_sizes[i] == NOUT * HID) W = (const float*)d_in[i];
        else if (in_sizes[i] == 1) {
            if (!t_syn) t_syn = (const float*)d_in[i];
            else        t_mem = (const float*)d_in[i];
        }
    }

    float* out = (float*)d_out;
    const int vol = SEQL * NCH;
    const int write_finals = (out_size >= vol + 2 * NCH) ? 1 : 0;

    static int smem_set = 0;
    if (!smem_set) {
        cudaFuncSetAttribute(snn_gemm_f16,
                             cudaFuncAttributeMaxDynamicSharedMemorySize, SMEMB);
        smem_set = 1;
    }

    w_preconv<<<(NOUT * HID) / 256, 256>>>(W);
    flag_reset<<<(SEG_P * NCH) / 256, 256>>>();
    snn_gemm_f16<<<MROWS / 128, 256, SMEMB>>>(x, out);
    scan_onepass<<<(SEG_P * NCH) / 256, 256>>>(out, out + vol, out + vol + NCH,
                                               t_syn, t_mem, write_finals);
}